// round 8
// baseline (speedup 1.0000x reference)
#include <cuda_runtime.h>
#include <cuda_fp16.h>
#include <cstdint>
#include <cstddef>
#include <math.h>

// ======================= device-global scratch (no allocs allowed) =======================
__device__ __align__(256) __half g_A[16777216];   // activations ping, 65536x256 max
__device__ __align__(256) __half g_B[16777216];   // activations pong
__device__ __align__(256) __half g_W[131072];     // WR_w fp16 [256,512]

// ======================= helpers =======================
__device__ __forceinline__ uint32_t smem_u32(const void* p) {
    uint32_t a;
    asm("{ .reg .u64 t; cvta.to.shared.u64 t, %1; cvt.u32.u64 %0, t; }" : "=r"(a) : "l"(p));
    return a;
}
__device__ __forceinline__ void cpa16(uint32_t dst, const void* src) {
    asm volatile("cp.async.cg.shared.global [%0], [%1], 16;" :: "r"(dst), "l"(src));
}
#define CP_COMMIT() asm volatile("cp.async.commit_group;" ::: "memory")
#define CP_WAIT(n)  asm volatile("cp.async.wait_group %0;" :: "n"(n) : "memory")

#define LDSM4(r0, r1, r2, r3, a) \
    asm volatile("ldmatrix.sync.aligned.m8n8.x4.shared.b16 {%0,%1,%2,%3}, [%4];" \
                 : "=r"(r0), "=r"(r1), "=r"(r2), "=r"(r3) : "r"(a))

__device__ __forceinline__ void mma16816(float* c, const uint32_t* a, uint32_t b0, uint32_t b1) {
    asm volatile(
        "mma.sync.aligned.m16n8k16.row.col.f32.f16.f16.f32 "
        "{%0,%1,%2,%3}, {%4,%5,%6,%7}, {%8,%9}, {%0,%1,%2,%3};"
        : "+f"(c[0]), "+f"(c[1]), "+f"(c[2]), "+f"(c[3])
        : "r"(a[0]), "r"(a[1]), "r"(a[2]), "r"(a[3]), "r"(b0), "r"(b1));
}

// ======================= common tile constants =======================
static constexpr int BM = 128, BN = 128, KC = 64;
static constexpr int NCH = 512 / KC;            // 8 chunks
static constexpr int RSTRIDE = 144;             // 128B data + 16B pad; ldsm conflict-free
static constexpr int TILE_B  = 128 * RSTRIDE;   // 18432 B
static constexpr int STAGE_B = 2 * TILE_B;      // A + W
static constexpr int NSTG = 3;
static constexpr int SMEM_BYTES = NSTG * STAGE_B;  // 110592 B -> 2 CTAs/SM

// fragment load helpers (8 regs each)
#define LDA8(d, sb, ks) do { \
    LDSM4((d)[0], (d)[1], (d)[2], (d)[3], (sb) + aOff + (ks) * 32); \
    LDSM4((d)[4], (d)[5], (d)[6], (d)[7], (sb) + aOff + (ks) * 32 + 16 * RSTRIDE); \
} while (0)
#define LDB8(d, sb, ks, half) do { \
    LDSM4((d)[0], (d)[1], (d)[2], (d)[3], \
          (sb) + wOff + (ks) * 32 + (half) * 32 * RSTRIDE); \
    LDSM4((d)[4], (d)[5], (d)[6], (d)[7], \
          (sb) + wOff + (ks) * 32 + ((half) * 32 + 16) * RSTRIDE); \
} while (0)

// ======================= level GEMM (single-term fp16 mma.sync) =======================
template <bool GATHER>
__global__ void __launch_bounds__(256, 2)
mma_level(const __half* __restrict__ Ain,
          const int* __restrict__ tokens, const float* __restrict__ embed,
          const float* __restrict__ bias, __half* __restrict__ Out) {
    extern __shared__ char sm[];
    __shared__ int stok[256];
    const uint32_t smb = smem_u32(sm);

    const int tid  = threadIdx.x;
    const int wid  = tid >> 5;
    const int lane = tid & 31;
    const int g    = lane >> 2;
    const int t    = lane & 3;
    const int m0 = (wid & 3) * 32;
    const int n0 = (wid >> 2) * 64;
    const int rowBase = blockIdx.x * BM;
    const int nBase   = blockIdx.y * BN;

    // ---- hoisted fill addressing ----
    const int u   = tid & 7;
    const int r0f = tid >> 3;                        // 0..31
    const __half* aSrc = GATHER ? nullptr
                                : Ain + (size_t)(rowBase + r0f) * 512 + u * 8;
    const __half* wSrc = g_W + (size_t)(nBase + r0f) * 512 + u * 8;
    const uint32_t dstOff = (uint32_t)r0f * RSTRIDE + u * 16;

    int tkA[4], tkB[4];
    if (GATHER) {
        int r = tid >> 1, j = tid & 1;
        int m = rowBase + r;
        stok[tid] = __ldg(&tokens[((m >> 8) << 9) + ((m & 255) << 1) + j]);
        __syncthreads();
#pragma unroll
        for (int i = 0; i < 4; ++i) {
            tkA[i] = stok[(r0f + 32 * i) * 2];
            tkB[i] = stok[(r0f + 32 * i) * 2 + 1];
        }
    }

    // ---- hoisted ldsm addressing ----
    const uint32_t lrow = lane & 15;
    const uint32_t lcol = (uint32_t)(lane >> 4) << 4;
    const uint32_t aOff = (uint32_t)(m0 + lrow) * RSTRIDE + lcol;
    const uint32_t wOff = TILE_B + (uint32_t)(n0 + lrow) * RSTRIDE + lcol;

    auto fill = [&](int c, int s) {
        if (GATHER) {
            // A: gather from fp32 embed table, convert, STS (visibility via barriers)
#pragma unroll
            for (int i = 0; i < 4; ++i) {
                int tok = (c >= 4) ? tkB[i] : tkA[i];
                const float4* src = reinterpret_cast<const float4*>(
                    embed + (size_t)tok * 256 + (c & 3) * 64 + u * 8);
                float4 v0 = __ldg(src);
                float4 v1 = __ldg(src + 1);
                __half2 h0 = __floats2half2_rn(v0.x, v0.y);
                __half2 h1 = __floats2half2_rn(v0.z, v0.w);
                __half2 h2 = __floats2half2_rn(v1.x, v1.y);
                __half2 h3 = __floats2half2_rn(v1.z, v1.w);
                uint4 pk;
                pk.x = *reinterpret_cast<uint32_t*>(&h0);
                pk.y = *reinterpret_cast<uint32_t*>(&h1);
                pk.z = *reinterpret_cast<uint32_t*>(&h2);
                pk.w = *reinterpret_cast<uint32_t*>(&h3);
                *reinterpret_cast<uint4*>(sm + s * STAGE_B + dstOff + i * 32 * RSTRIDE) = pk;
            }
        } else {
#pragma unroll
            for (int i = 0; i < 4; ++i)
                cpa16(smb + s * STAGE_B + dstOff + i * 32 * RSTRIDE,
                      aSrc + i * 16384 + c * 64);
        }
#pragma unroll
        for (int i = 0; i < 4; ++i)
            cpa16(smb + s * STAGE_B + TILE_B + dstOff + i * 32 * RSTRIDE,
                  wSrc + i * 16384 + c * 64);
        CP_COMMIT();
    };

    float acc[2][8][4];
#pragma unroll
    for (int mt = 0; mt < 2; ++mt)
#pragma unroll
        for (int nt = 0; nt < 8; ++nt)
#pragma unroll
            for (int j = 0; j < 4; ++j) acc[mt][nt][j] = 0.0f;

    auto mmah = [&](int half, const uint32_t* a, const uint32_t* b) {
#pragma unroll
        for (int jj = 0; jj < 2; ++jj)
#pragma unroll
            for (int sub = 0; sub < 2; ++sub) {
                const int nt = half * 4 + jj * 2 + sub;
                const uint32_t b0 = b[jj * 4 + sub], b1 = b[jj * 4 + sub + 2];
                mma16816(acc[0][nt], a,     b0, b1);
                mma16816(acc[1][nt], a + 4, b0, b1);
            }
    };

    fill(0, 0);
    fill(1, 1);

#pragma unroll
    for (int c = 0; c < NCH; ++c) {
        if (c < NCH - 1) { CP_WAIT(1); } else { CP_WAIT(0); }
        __syncthreads();

        const uint32_t sb = smb + (c % NSTG) * STAGE_B;
        uint32_t af[2][8], bf[2][8];
        LDA8(af[0], sb, 0);
        LDB8(bf[0], sb, 0, 0);
#pragma unroll
        for (int ks = 0; ks < 4; ++ks) {
            LDB8(bf[1], sb, ks, 1);
            mmah(0, af[ks & 1], bf[0]);
            if (ks < 3) {
                LDA8(af[(ks + 1) & 1], sb, ks + 1);
                LDB8(bf[0], sb, ks + 1, 0);
            }
            mmah(1, af[ks & 1], bf[1]);
        }

        // fill AFTER the MMA block: LDG stall (gather) overlaps this chunk's MMAs
        if (c + 2 < NCH) fill(c + 2, (c + 2) % NSTG);
    }

    // ---- epilogue: +bias, tanh, fp16 store ----
#pragma unroll
    for (int mt = 0; mt < 2; ++mt) {
#pragma unroll
        for (int nt = 0; nt < 8; ++nt) {
            const int col = nBase + n0 + nt * 8 + 2 * t;
            const float b0 = __ldg(&bias[col]);
            const float b1 = __ldg(&bias[col + 1]);
#pragma unroll
            for (int h = 0; h < 2; ++h) {
                const int row = rowBase + m0 + mt * 16 + g + h * 8;
                float v0 = tanhf(acc[mt][nt][2 * h]     + b0);
                float v1 = tanhf(acc[mt][nt][2 * h + 1] + b1);
                *reinterpret_cast<__half2*>(Out + (size_t)row * 256 + col) =
                    __floats2half2_rn(v0, v1);
            }
        }
    }
}

// ======================= fused tail: levels 4..8 + head in one kernel =======================
// 32 CTAs; CTA b handles 8 batches (lvl4-out rows [128b,128b+128)).
static constexpr int PSTR   = 1040;               // 1024B row + 16B pad
static constexpr int TSTAGE = 2 * TILE_B;         // W tile + A tile = 36864 B
static constexpr int ACT0_OFF  = NSTG * TSTAGE;              // 110592
static constexpr int ACT1_OFF  = ACT0_OFF + 64 * PSTR;       // +66560
static constexpr int TAIL_SMEM = ACT1_OFF + 32 * PSTR;       // 210432 B
// roots/hidden reuse ACT0 region (free once lvl8 reads ACT1)
static constexpr int ROOTS_OFF  = ACT0_OFF;                  // float [8][264]
static constexpr int HIDDEN_OFF = ROOTS_OFF + 8 * 264 * 4;   // float [8][264]

__global__ void __launch_bounds__(256, 1)
tail_kernel(const __half* __restrict__ Ain,       // lvl3 out, viewed [4096, 512]
            const float* __restrict__ bias,
            const float* __restrict__ WF, const float* __restrict__ bF,
            const float* __restrict__ WO, const float* __restrict__ bO,
            float* __restrict__ out) {
    extern __shared__ char sm[];
    const uint32_t smb = smem_u32(sm);

    const int tid  = threadIdx.x;
    const int wid  = tid >> 5;
    const int lane = tid & 31;
    const int g    = lane >> 2;
    const int t    = lane & 3;
    const int m0 = (wid & 3) * 32;
    const int n0 = (wid >> 2) * 64;
    const int bid = blockIdx.x;

    const int u   = tid & 7;
    const int r0f = tid >> 3;
    const uint32_t dstOff = (uint32_t)r0f * RSTRIDE + u * 16;
    const uint32_t lrow = lane & 15;
    const uint32_t lcol = (uint32_t)(lane >> 4) << 4;
    const uint32_t aOffS = (uint32_t)(m0 + lrow) * RSTRIDE + lcol;
    const __half* aG = Ain + (size_t)(128 * bid) * 512;   // this CTA's lvl4 A rows

    auto run_level = [&](int M, bool stageA, uint32_t actInOff, int outMode,
                         uint32_t actOutOff) {
        const bool mact = (m0 < M);
#pragma unroll 1
        for (int np = 0; np < 2; ++np) {
            const int nb = np * 128;
            const __half* wSrc = g_W + (size_t)(nb + r0f) * 512 + u * 8;

            auto fillT = [&](int c, int s) {
                const uint32_t sb = smb + s * TSTAGE;
#pragma unroll
                for (int i = 0; i < 4; ++i)
                    cpa16(sb + dstOff + i * 32 * RSTRIDE, wSrc + i * 16384 + c * 64);
                if (stageA) {
#pragma unroll
                    for (int i = 0; i < 4; ++i)
                        cpa16(sb + TILE_B + dstOff + i * 32 * RSTRIDE,
                              aG + (size_t)(r0f + 32 * i) * 512 + u * 8 + c * 64);
                }
                CP_COMMIT();
            };

            float acc[2][8][4];
#pragma unroll
            for (int mt = 0; mt < 2; ++mt)
#pragma unroll
                for (int nt = 0; nt < 8; ++nt)
#pragma unroll
                    for (int j = 0; j < 4; ++j) acc[mt][nt][j] = 0.0f;

            fillT(0, 0);
            fillT(1, 1);

#pragma unroll 1
            for (int c = 0; c < NCH; ++c) {
                if (c < NCH - 1) { CP_WAIT(1); } else { CP_WAIT(0); }
                __syncthreads();
                if (c + 2 < NCH) fillT(c + 2, (c + 2) % NSTG);

                const uint32_t sb = smb + (c % NSTG) * TSTAGE;
                if (mact) {
#pragma unroll
                    for (int ks = 0; ks < 4; ++ks) {
                        uint32_t a[2][4];
                        if (stageA) {
                            LDSM4(a[0][0], a[0][1], a[0][2], a[0][3],
                                  sb + TILE_B + aOffS + ks * 32);
                            LDSM4(a[1][0], a[1][1], a[1][2], a[1][3],
                                  sb + TILE_B + aOffS + ks * 32 + 16 * RSTRIDE);
                        } else {
                            const uint32_t ab = smb + actInOff +
                                (uint32_t)(m0 + lrow) * PSTR + c * 128 + ks * 32 + lcol;
                            LDSM4(a[0][0], a[0][1], a[0][2], a[0][3], ab);
                            LDSM4(a[1][0], a[1][1], a[1][2], a[1][3], ab + 16 * PSTR);
                        }
#pragma unroll
                        for (int half = 0; half < 2; ++half) {
                            uint32_t b[8];
                            const uint32_t wb = sb + (uint32_t)(n0 + lrow) * RSTRIDE + lcol +
                                                ks * 32 + half * 32 * RSTRIDE;
                            LDSM4(b[0], b[1], b[2], b[3], wb);
                            LDSM4(b[4], b[5], b[6], b[7], wb + 16 * RSTRIDE);
#pragma unroll
                            for (int jj = 0; jj < 2; ++jj) {
#pragma unroll
                                for (int sub = 0; sub < 2; ++sub) {
                                    const int nt = half * 4 + jj * 2 + sub;
                                    const uint32_t b0 = b[jj * 4 + sub];
                                    const uint32_t b1 = b[jj * 4 + sub + 2];
                                    mma16816(acc[0][nt], a[0], b0, b1);
                                    mma16816(acc[1][nt], a[1], b0, b1);
                                }
                            }
                        }
                    }
                }
            }

            if (mact) {
#pragma unroll
                for (int mt = 0; mt < 2; ++mt) {
#pragma unroll
                    for (int nt = 0; nt < 8; ++nt) {
                        const int col = nb + n0 + nt * 8 + 2 * t;
                        const float b0 = __ldg(&bias[col]);
                        const float b1 = __ldg(&bias[col + 1]);
#pragma unroll
                        for (int h = 0; h < 2; ++h) {
                            const int row = m0 + mt * 16 + g + h * 8;
                            if (row < M) {
                                float v0 = tanhf(acc[mt][nt][2 * h]     + b0);
                                float v1 = tanhf(acc[mt][nt][2 * h + 1] + b1);
                                if (outMode == 0) {
                                    __half2 hv = __floats2half2_rn(v0, v1);
                                    uint32_t ad = smb + actOutOff + (row >> 1) * PSTR +
                                                  (((row & 1) << 8) + col) * 2;
                                    asm volatile("st.shared.b32 [%0], %1;"
                                                 :: "r"(ad),
                                                    "r"(*reinterpret_cast<uint32_t*>(&hv))
                                                 : "memory");
                                } else {
                                    // roots as fp32 [8][264]
                                    float2 rv = make_float2(v0, v1);
                                    *reinterpret_cast<float2*>(
                                        sm + ROOTS_OFF + row * 264 * 4 + col * 4) = rv;
                                }
                            }
                        }
                    }
                }
            }
            __syncthreads();
        }
    };

    run_level(128, true,  0,        0, ACT0_OFF);   // lvl4 (A from global)
    run_level(64,  false, ACT0_OFF, 0, ACT1_OFF);   // lvl5
    run_level(32,  false, ACT1_OFF, 0, ACT0_OFF);   // lvl6
    run_level(16,  false, ACT0_OFF, 0, ACT1_OFF);   // lvl7
    run_level(8,   false, ACT1_OFF, 1, 0);          // lvl8 -> roots (smem fp32)

    // ---- inline head: hidden = relu(root @ WF^T + bF); out = hidden @ WO^T + bO ----
    const float* rootsS = reinterpret_cast<const float*>(sm + ROOTS_OFF);
    float* hiddenS      = reinterpret_cast<float*>(sm + HIDDEN_OFF);
    {
        const int h = tid;                       // hidden unit
        const float* wrow = WF + (size_t)h * 256;
        float accb[8];
        const float hb = __ldg(&bF[h]);
#pragma unroll
        for (int b = 0; b < 8; ++b) accb[b] = hb;
        for (int d = 0; d < 256; d += 4) {
            float4 w4 = *reinterpret_cast<const float4*>(wrow + d);
#pragma unroll
            for (int b = 0; b < 8; ++b) {
                const float* rb = rootsS + b * 264 + d;
                accb[b] += rb[0] * w4.x + rb[1] * w4.y + rb[2] * w4.z + rb[3] * w4.w;
            }
        }
#pragma unroll
        for (int b = 0; b < 8; ++b) hiddenS[b * 264 + h] = fmaxf(accb[b], 0.0f);
    }
    __syncthreads();
    {
        const int b = wid;                       // one warp per batch
        const float* hrow = hiddenS + b * 264;
#pragma unroll
        for (int c = 0; c < 5; ++c) {
            float s = 0.0f;
            for (int d = lane; d < 256; d += 32) s += hrow[d] * __ldg(&WO[c * 256 + d]);
#pragma unroll
            for (int o = 16; o; o >>= 1) s += __shfl_down_sync(0xffffffffu, s, o);
            if (lane == 0) out[(size_t)(8 * bid + b) * 5 + c] = s + __ldg(&bO[c]);
        }
    }
}

// ======================= fp16 weight conversion (one-time) =======================
__global__ void __launch_bounds__(256)
weight_split(const float* __restrict__ W) {
    int i = blockIdx.x * 256 + threadIdx.x;        // 131072 elems
    g_W[i] = __float2half_rn(W[i]);
}

// ======================= launch =======================
extern "C" void kernel_launch(void* const* d_in, const int* in_sizes, int n_in,
                              void* d_out, int out_size) {
    (void)in_sizes; (void)n_in; (void)out_size;
    const int*   tokens = (const int*)  d_in[0];
    const float* embed  = (const float*)d_in[1];
    const float* WR_w   = (const float*)d_in[2];
    const float* WR_b   = (const float*)d_in[3];
    const float* WF_w   = (const float*)d_in[4];
    const float* WF_b   = (const float*)d_in[5];
    const float* WO_w   = (const float*)d_in[6];
    const float* WO_b   = (const float*)d_in[7];
    float* out = (float*)d_out;

    cudaFuncSetAttribute(mma_level<true>,  cudaFuncAttributeMaxDynamicSharedMemorySize, SMEM_BYTES);
    cudaFuncSetAttribute(mma_level<false>, cudaFuncAttributeMaxDynamicSharedMemorySize, SMEM_BYTES);
    cudaFuncSetAttribute(tail_kernel,      cudaFuncAttributeMaxDynamicSharedMemorySize, TAIL_SMEM);

    __half *A, *B;
    cudaGetSymbolAddress((void**)&A, g_A);
    cudaGetSymbolAddress((void**)&B, g_B);

    weight_split<<<512, 256>>>(WR_w);

    // level 0: fused fp32-embedding gather, out -> g_A
    {
        dim3 grid(65536 / BM, 2);
        mma_level<true><<<grid, 256, SMEM_BYTES>>>(nullptr, tokens, embed, WR_b, A);
    }
    // levels 1..3: ping-pong  (lvl1 A->B, lvl2 B->A, lvl3 A->B)
    for (int lvl = 1; lvl <= 3; ++lvl) {
        int M = 65536 >> lvl;
        dim3 grid(M / BM, 2);
        const __half* in = (lvl & 1) ? A : B;
        __half*       ot = (lvl & 1) ? B : A;
        mma_level<false><<<grid, 256, SMEM_BYTES>>>(in, nullptr, nullptr, WR_b, ot);
    }
    // levels 4..8 + head fused; writes d_out
    tail_kernel<<<32, 256, TAIL_SMEM>>>(B, WR_b, WF_w, WF_b, WO_w, WO_b, out);
}

// round 9
// speedup vs baseline: 1.1385x; 1.1385x over previous
#include <cuda_runtime.h>
#include <cuda_fp16.h>
#include <cstdint>
#include <cstddef>
#include <math.h>

// ======================= device-global scratch (no allocs allowed) =======================
__device__ __align__(256) __half g_A[16777216];   // activations ping, 65536x256 max
__device__ __align__(256) __half g_B[16777216];   // activations pong
__device__ __align__(256) __half g_W[131072];     // WR_w fp16 [256,512]

// ======================= helpers =======================
__device__ __forceinline__ uint32_t smem_u32(const void* p) {
    uint32_t a;
    asm("{ .reg .u64 t; cvta.to.shared.u64 t, %1; cvt.u32.u64 %0, t; }" : "=r"(a) : "l"(p));
    return a;
}
__device__ __forceinline__ void cpa16(uint32_t dst, const void* src) {
    asm volatile("cp.async.cg.shared.global [%0], [%1], 16;" :: "r"(dst), "l"(src));
}
#define CP_COMMIT() asm volatile("cp.async.commit_group;" ::: "memory")
#define CP_WAIT(n)  asm volatile("cp.async.wait_group %0;" :: "n"(n) : "memory")

#define LDSM4(r0, r1, r2, r3, a) \
    asm volatile("ldmatrix.sync.aligned.m8n8.x4.shared.b16 {%0,%1,%2,%3}, [%4];" \
                 : "=r"(r0), "=r"(r1), "=r"(r2), "=r"(r3) : "r"(a))

__device__ __forceinline__ void mma16816(float* c, const uint32_t* a, uint32_t b0, uint32_t b1) {
    asm volatile(
        "mma.sync.aligned.m16n8k16.row.col.f32.f16.f16.f32 "
        "{%0,%1,%2,%3}, {%4,%5,%6,%7}, {%8,%9}, {%0,%1,%2,%3};"
        : "+f"(c[0]), "+f"(c[1]), "+f"(c[2]), "+f"(c[3])
        : "r"(a[0]), "r"(a[1]), "r"(a[2]), "r"(a[3]), "r"(b0), "r"(b1));
}

// ======================= common tile constants =======================
static constexpr int BM = 128, BN = 128, KC = 64;
static constexpr int NCH = 512 / KC;            // 8 chunks
static constexpr int RSTRIDE = 144;             // 128B data + 16B pad; ldsm conflict-free
static constexpr int TILE_B  = 128 * RSTRIDE;   // 18432 B
static constexpr int STAGE_B = 2 * TILE_B;      // A + W
static constexpr int NSTG = 3;
static constexpr int SMEM_BYTES = NSTG * STAGE_B;  // 110592 B -> 2 CTAs/SM

// fragment load helpers (8 regs each)
#define LDA8(d, sb, ks) do { \
    LDSM4((d)[0], (d)[1], (d)[2], (d)[3], (sb) + aOff + (ks) * 32); \
    LDSM4((d)[4], (d)[5], (d)[6], (d)[7], (sb) + aOff + (ks) * 32 + 16 * RSTRIDE); \
} while (0)
#define LDB8(d, sb, ks, half) do { \
    LDSM4((d)[0], (d)[1], (d)[2], (d)[3], \
          (sb) + wOff + (ks) * 32 + (half) * 32 * RSTRIDE); \
    LDSM4((d)[4], (d)[5], (d)[6], (d)[7], \
          (sb) + wOff + (ks) * 32 + ((half) * 32 + 16) * RSTRIDE); \
} while (0)

// ======================= level GEMM (single-term fp16 mma.sync) =======================
// out[M,256] = tanh(A[M,512] @ W[256,512]^T + bias), fp16 in/out, fp32 accum.
// CTA 128x128, 8 warps (4 M x 2 N), warp tile 32x64. KC=64, 3-stage cp.async ring.
template <bool GATHER>
__global__ void __launch_bounds__(256, 2)
mma_level(const __half* __restrict__ Ain,
          const int* __restrict__ tokens, const float* __restrict__ embed,
          const float* __restrict__ bias, __half* __restrict__ Out) {
    extern __shared__ char sm[];
    __shared__ int stok[256];
    const uint32_t smb = smem_u32(sm);

    const int tid  = threadIdx.x;
    const int wid  = tid >> 5;
    const int lane = tid & 31;
    const int g    = lane >> 2;
    const int t    = lane & 3;
    const int m0 = (wid & 3) * 32;
    const int n0 = (wid >> 2) * 64;
    const int rowBase = blockIdx.x * BM;
    const int nBase   = blockIdx.y * BN;
    const int kso  = (wid & 1) * 2;               // ks stagger: odd warps start at ks=2

    // ---- hoisted fill addressing ----
    const int u   = tid & 7;
    const int r0f = tid >> 3;                        // 0..31
    const __half* aSrc = GATHER ? nullptr
                                : Ain + (size_t)(rowBase + r0f) * 512 + u * 8;
    const __half* wSrc = g_W + (size_t)(nBase + r0f) * 512 + u * 8;
    const uint32_t dstOff = (uint32_t)r0f * RSTRIDE + u * 16;

    int tkA[4], tkB[4];
    if (GATHER) {
        int r = tid >> 1, j = tid & 1;
        int m = rowBase + r;
        stok[tid] = __ldg(&tokens[((m >> 8) << 9) + ((m & 255) << 1) + j]);
        __syncthreads();
#pragma unroll
        for (int i = 0; i < 4; ++i) {
            tkA[i] = stok[(r0f + 32 * i) * 2];
            tkB[i] = stok[(r0f + 32 * i) * 2 + 1];
        }
    }

    // ---- hoisted ldsm addressing ----
    const uint32_t lrow = lane & 15;
    const uint32_t lcol = (uint32_t)(lane >> 4) << 4;
    const uint32_t aOff = (uint32_t)(m0 + lrow) * RSTRIDE + lcol;
    const uint32_t wOff = TILE_B + (uint32_t)(n0 + lrow) * RSTRIDE + lcol;

    auto fill = [&](int c, int s) {
        if (GATHER) {
            // A: gather from fp32 embed table, convert, STS (visible after next barrier)
#pragma unroll
            for (int i = 0; i < 4; ++i) {
                int tok = (c >= 4) ? tkB[i] : tkA[i];
                const float4* src = reinterpret_cast<const float4*>(
                    embed + (size_t)tok * 256 + (c & 3) * 64 + u * 8);
                float4 v0 = __ldg(src);
                float4 v1 = __ldg(src + 1);
                __half2 h0 = __floats2half2_rn(v0.x, v0.y);
                __half2 h1 = __floats2half2_rn(v0.z, v0.w);
                __half2 h2 = __floats2half2_rn(v1.x, v1.y);
                __half2 h3 = __floats2half2_rn(v1.z, v1.w);
                uint4 pk;
                pk.x = *reinterpret_cast<uint32_t*>(&h0);
                pk.y = *reinterpret_cast<uint32_t*>(&h1);
                pk.z = *reinterpret_cast<uint32_t*>(&h2);
                pk.w = *reinterpret_cast<uint32_t*>(&h3);
                *reinterpret_cast<uint4*>(sm + s * STAGE_B + dstOff + i * 32 * RSTRIDE) = pk;
            }
        } else {
#pragma unroll
            for (int i = 0; i < 4; ++i)
                cpa16(smb + s * STAGE_B + dstOff + i * 32 * RSTRIDE,
                      aSrc + i * 16384 + c * 64);
        }
#pragma unroll
        for (int i = 0; i < 4; ++i)
            cpa16(smb + s * STAGE_B + TILE_B + dstOff + i * 32 * RSTRIDE,
                  wSrc + i * 16384 + c * 64);
        CP_COMMIT();
    };

    float acc[2][8][4];
#pragma unroll
    for (int mt = 0; mt < 2; ++mt)
#pragma unroll
        for (int nt = 0; nt < 8; ++nt)
#pragma unroll
            for (int j = 0; j < 4; ++j) acc[mt][nt][j] = 0.0f;

    fill(0, 0);
    fill(1, 1);

#pragma unroll
    for (int c = 0; c < NCH; ++c) {
        if (c < NCH - 1) { CP_WAIT(1); } else { CP_WAIT(0); }
        __syncthreads();
        // regular levels: issue next-stage cp.async BEFORE MMAs (proven layout)
        if (!GATHER && c + 2 < NCH) fill(c + 2, (c + 2) % NSTG);

        const uint32_t sb = smb + (c % NSTG) * STAGE_B;
#pragma unroll
        for (int ks2 = 0; ks2 < 4; ++ks2) {
            const int ks = (ks2 + kso) & 3;       // staggered k16 order (accum-order free)
            uint32_t a[2][4];
            LDSM4(a[0][0], a[0][1], a[0][2], a[0][3], sb + aOff + ks * 32);
            LDSM4(a[1][0], a[1][1], a[1][2], a[1][3], sb + aOff + ks * 32 + 16 * RSTRIDE);
#pragma unroll
            for (int half = 0; half < 2; ++half) {
                uint32_t b[8];
                LDSM4(b[0], b[1], b[2], b[3], sb + wOff + ks * 32 + half * 32 * RSTRIDE);
                LDSM4(b[4], b[5], b[6], b[7], sb + wOff + ks * 32 + (half * 32 + 16) * RSTRIDE);
#pragma unroll
                for (int jj = 0; jj < 2; ++jj) {
#pragma unroll
                    for (int sub = 0; sub < 2; ++sub) {
                        const int nt = half * 4 + jj * 2 + sub;
                        const uint32_t b0 = b[jj * 4 + sub], b1 = b[jj * 4 + sub + 2];
                        mma16816(acc[0][nt], a[0], b0, b1);
                        mma16816(acc[1][nt], a[1], b0, b1);
                    }
                }
            }
        }

        // gather level: fill AFTER MMAs so the synchronous LDG chain overlaps compute
        if (GATHER && c + 2 < NCH) fill(c + 2, (c + 2) % NSTG);
    }

    // ---- epilogue: +bias, tanh, fp16 store ----
#pragma unroll
    for (int mt = 0; mt < 2; ++mt) {
#pragma unroll
        for (int nt = 0; nt < 8; ++nt) {
            const int col = nBase + n0 + nt * 8 + 2 * t;
            const float b0 = __ldg(&bias[col]);
            const float b1 = __ldg(&bias[col + 1]);
#pragma unroll
            for (int h = 0; h < 2; ++h) {
                const int row = rowBase + m0 + mt * 16 + g + h * 8;
                float v0 = tanhf(acc[mt][nt][2 * h]     + b0);
                float v1 = tanhf(acc[mt][nt][2 * h + 1] + b1);
                *reinterpret_cast<__half2*>(Out + (size_t)row * 256 + col) =
                    __floats2half2_rn(v0, v1);
            }
        }
    }
}

// ======================= fp16 weight conversion (one-time) =======================
__global__ void __launch_bounds__(256)
weight_split(const float* __restrict__ W) {
    int i = blockIdx.x * 256 + threadIdx.x;        // 131072 elems
    g_W[i] = __float2half_rn(W[i]);
}

// ======================= head =======================
__global__ void __launch_bounds__(256)
head_kernel(const __half* __restrict__ root,      // [256, 256] fp16
            const float* __restrict__ WF, const float* __restrict__ bF,
            const float* __restrict__ WO, const float* __restrict__ bO,
            float* __restrict__ out) {
    __shared__ float r[256];
    __shared__ float h[256];
    int b = blockIdx.x, t = threadIdx.x;
    r[t] = __half2float(root[b * 256 + t]);
    __syncthreads();
    float acc = bF[t];
    const float* w = WF + (size_t)t * 256;
#pragma unroll 8
    for (int d = 0; d < 256; d += 4) {
        float4 w4 = *reinterpret_cast<const float4*>(w + d);
        acc += r[d] * w4.x + r[d + 1] * w4.y + r[d + 2] * w4.z + r[d + 3] * w4.w;
    }
    h[t] = fmaxf(acc, 0.0f);
    __syncthreads();
    int wid = t >> 5, lane = t & 31;
    if (wid < 5) {
        float s = 0.0f;
        for (int i = lane; i < 256; i += 32) s += h[i] * WO[wid * 256 + i];
#pragma unroll
        for (int o = 16; o; o >>= 1) s += __shfl_down_sync(0xffffffffu, s, o);
        if (lane == 0) out[b * 5 + wid] = s + bO[wid];
    }
}

// ======================= launch =======================
extern "C" void kernel_launch(void* const* d_in, const int* in_sizes, int n_in,
                              void* d_out, int out_size) {
    (void)in_sizes; (void)n_in; (void)out_size;
    const int*   tokens = (const int*)  d_in[0];
    const float* embed  = (const float*)d_in[1];
    const float* WR_w   = (const float*)d_in[2];
    const float* WR_b   = (const float*)d_in[3];
    const float* WF_w   = (const float*)d_in[4];
    const float* WF_b   = (const float*)d_in[5];
    const float* WO_w   = (const float*)d_in[6];
    const float* WO_b   = (const float*)d_in[7];
    float* out = (float*)d_out;

    cudaFuncSetAttribute(mma_level<true>,  cudaFuncAttributeMaxDynamicSharedMemorySize, SMEM_BYTES);
    cudaFuncSetAttribute(mma_level<false>, cudaFuncAttributeMaxDynamicSharedMemorySize, SMEM_BYTES);

    __half *A, *B;
    cudaGetSymbolAddress((void**)&A, g_A);
    cudaGetSymbolAddress((void**)&B, g_B);

    weight_split<<<512, 256>>>(WR_w);

    // level 0: fused fp32-embedding gather, out -> g_A
    {
        dim3 grid(65536 / BM, 2);
        mma_level<true><<<grid, 256, SMEM_BYTES>>>(nullptr, tokens, embed, WR_b, A);
    }
    // levels 1..8: ping-pong  (odd: A->B, even: B->A); lvl8 out -> g_A
    for (int lvl = 1; lvl <= 8; ++lvl) {
        int M = 65536 >> lvl;
        dim3 grid(M / BM, 2);
        const __half* in = (lvl & 1) ? A : B;
        __half*       ot = (lvl & 1) ? B : A;
        mma_level<false><<<grid, 256, SMEM_BYTES>>>(in, nullptr, nullptr, WR_b, ot);
    }
    // root in g_A: [256, 256]
    head_kernel<<<256, 256>>>(A, WF_w, WF_b, WO_w, WO_b, out);
}